// round 5
// baseline (speedup 1.0000x reference)
#include <cuda_runtime.h>
#include <cstdint>

#define BATCH   8
#define CIN     256
#define HWPX    4096
#define WIDTH   64
#define CR      64
#define GROUPS  32
#define GCH     8

// intermediate y = relu6(bn(conv1(x)))  : [B][64][4096] = 8.4 MB (L2-resident)
__device__ __align__(16) float g_y[(size_t)BATCH * CR * HWPX];

typedef unsigned long long u64;

// ---------------- packed f32x2 helpers ----------------
__device__ __forceinline__ u64 ffma2(u64 a, u64 b, u64 c) {
    u64 d;
    asm("fma.rn.f32x2 %0, %1, %2, %3;" : "=l"(d) : "l"(a), "l"(b), "l"(c));
    return d;
}
__device__ __forceinline__ u64 add2(u64 a, u64 b) {
    u64 d;
    asm("add.rn.f32x2 %0, %1, %2;" : "=l"(d) : "l"(a), "l"(b));
    return d;
}
__device__ __forceinline__ u64 pack2(float lo, float hi) {
    u64 d;
    asm("mov.b64 %0, {%1, %2};" : "=l"(d) : "f"(lo), "f"(hi));
    return d;
}
__device__ __forceinline__ float2 unpack2(u64 v) {
    float2 r;
    asm("mov.b64 {%0, %1}, %2;" : "=f"(r.x), "=f"(r.y) : "l"(v));
    return r;
}

// ---------------------------------------------------------------------------
// K1: conv1 (256->64) + BN + ReLU6 -> g_y
// grid (64 px-tiles of 64, 8 batch), 256 threads, 2 CTAs/SM
// smem: w1t [256ci][64co] f32 transposed (64KB); row = 16 ulonglong2
// thread: 4 px (quad) x 4 co, x via LDG (read once chip-wide), no mainloop sync
// ---------------------------------------------------------------------------
__global__ void __launch_bounds__(256, 2)
k1_conv1(const float* __restrict__ x,
         const float* __restrict__ w1, const float* __restrict__ b1,
         const float* __restrict__ gma, const float* __restrict__ bta,
         const float* __restrict__ mu,  const float* __restrict__ var)
{
    extern __shared__ float w1t[];                       // [256][64]
    const ulonglong2* w1tv = reinterpret_cast<const ulonglong2*>(w1t); // [256][16]

    const int tid = threadIdx.x;
    const int q   = tid & 15;          // px quad within 64-px tile
    const int cg  = tid >> 4;          // co group: 4 co = 1 ulonglong2
    const int b   = blockIdx.y;
    const int px0 = blockIdx.x * 64;

    // stage w1 transposed: w1t[ci][co] = w1[co][ci]
    #pragma unroll 8
    for (int k = 0; k < 64; ++k) {
        int i  = tid + k * 256;
        int co = i & 63, ci = i >> 6;
        w1t[ci * 64 + co] = w1[co * 256 + ci];
    }
    __syncthreads();

    u64 acc[2][4];
    #pragma unroll
    for (int c = 0; c < 2; ++c)
        #pragma unroll
        for (int j = 0; j < 4; ++j) acc[c][j] = 0ull;

    const float4* x4 = reinterpret_cast<const float4*>(x + (size_t)b * CIN * HWPX + px0) + q;

    float4 xv = x4[0];
    #pragma unroll 4
    for (int ci = 0; ci < 256; ++ci) {
        float4 xn = (ci < 255) ? x4[(ci + 1) * (HWPX / 4)] : xv;
        ulonglong2 wv = w1tv[ci * 16 + cg];   // {co0,co1},{co2,co3}
        u64 xx0 = pack2(xv.x, xv.x);
        u64 xx1 = pack2(xv.y, xv.y);
        u64 xx2 = pack2(xv.z, xv.z);
        u64 xx3 = pack2(xv.w, xv.w);
        acc[0][0] = ffma2(wv.x, xx0, acc[0][0]);
        acc[1][0] = ffma2(wv.y, xx0, acc[1][0]);
        acc[0][1] = ffma2(wv.x, xx1, acc[0][1]);
        acc[1][1] = ffma2(wv.y, xx1, acc[1][1]);
        acc[0][2] = ffma2(wv.x, xx2, acc[0][2]);
        acc[1][2] = ffma2(wv.y, xx2, acc[1][2]);
        acc[0][3] = ffma2(wv.x, xx3, acc[0][3]);
        acc[1][3] = ffma2(wv.y, xx3, acc[1][3]);
        xv = xn;
    }

    // BN + ReLU6 + store
    float4* y4 = reinterpret_cast<float4*>(g_y + (size_t)b * CR * HWPX + px0) + q;
    #pragma unroll
    for (int cp = 0; cp < 2; ++cp) {
        int co0 = cg * 4 + 2 * cp, co1 = co0 + 1;
        float s0  = __ldg(&gma[co0]) * rsqrtf(__ldg(&var[co0]) + 1e-5f);
        float bb0 = fmaf(__ldg(&b1[co0]), s0, __ldg(&bta[co0]) - __ldg(&mu[co0]) * s0);
        float s1  = __ldg(&gma[co1]) * rsqrtf(__ldg(&var[co1]) + 1e-5f);
        float bb1 = fmaf(__ldg(&b1[co1]), s1, __ldg(&bta[co1]) - __ldg(&mu[co1]) * s1);
        float4 r0, r1;
        float* r0f = reinterpret_cast<float*>(&r0);
        float* r1f = reinterpret_cast<float*>(&r1);
        #pragma unroll
        for (int j = 0; j < 4; ++j) {
            float2 f = unpack2(acc[cp][j]);
            r0f[j] = fminf(fmaxf(fmaf(f.x, s0, bb0), 0.f), 6.f);
            r1f[j] = fminf(fmaxf(fmaf(f.y, s1, bb1), 0.f), 6.f);
        }
        y4[(size_t)co0 * (HWPX / 4)] = r0;
        y4[(size_t)co1 * (HWPX / 4)] = r1;
    }
}

// ---------------------------------------------------------------------------
// K2: fused conv2 + involution, 5 tap-row passes (involution linear in taps)
// grid (4 h-tiles of 16 rows, 32 groups, 8 batch) = 1024 CTAs, 256 th, 3 CTAs/SM
// smem: xh [8ch][20r][72c] = 46080B | w2d [64cr][5ti][6 u64 dup] = 15360B
// y read via coalesced LDG from L2 (5x re-read, no staging, no mainloop syncs)
// thread: one 4-px quad; per pass: ka[5 taps][2 pxpairs] = 10 u64; out 16 u64.
// ---------------------------------------------------------------------------
__global__ void __launch_bounds__(256, 3)
k2_fused(const float* __restrict__ x,
         const float* __restrict__ w2, const float* __restrict__ b2,
         float* __restrict__ out)
{
    extern __shared__ char smraw[];
    float* xh = reinterpret_cast<float*>(smraw);                     // 46080 B
    const float4* xh4 = reinterpret_cast<const float4*>(smraw);
    u64* w2d = reinterpret_cast<u64*>(smraw + 46080);                // [64][5][6]

    const int tid = threadIdx.x;
    const int b   = blockIdx.z;
    const int g   = blockIdx.y;
    const int h0  = blockIdx.x * 16;
    const int px0 = h0 * WIDTH;
    const int q   = tid;          // quad: px = px0 + 4q
    const int r   = q >> 4;       // tile row 0..15
    const int c4  = q & 15;       // col quad

    // ---- stage x halo: 8 ch x 20 rows x 68 cols, pitch 72 ----
    const float* xb = x + ((size_t)b * CIN + g * GCH) * HWPX;
    for (int i = tid; i < 8 * 20 * 68; i += 256) {
        int c   = i / 1360;
        int rem = i - c * 1360;
        int rr  = rem / 68;
        int col = rem - rr * 68;
        int hy = h0 - 2 + rr, wx = col - 2;
        float v = 0.f;
        if ((unsigned)hy < 64u && (unsigned)wx < 64u)
            v = xb[c * HWPX + hy * WIDTH + wx];
        xh[c * 1440 + rr * 72 + col] = v;
    }
    // ---- stage w2 dup pairs: w2d[cr][ti][j] = {w,w}, j=5 pad ----
    for (int i = tid; i < 64 * 30; i += 256) {
        int cr  = i / 30;
        int rem = i - cr * 30;
        int ti  = rem / 6;
        int j   = rem - ti * 6;
        float v = (j < 5) ? w2[(size_t)(g * 25 + ti * 5 + j) * 64 + cr] : 0.f;
        w2d[cr * 30 + ti * 6 + j] = pack2(v, v);
    }
    __syncthreads();

    u64 o0[8], o1[8];
    #pragma unroll
    for (int c = 0; c < 8; ++c) { o0[c] = 0ull; o1[c] = 0ull; }

    // ulonglong2 = 4 floats -> one y channel = HWPX/4 = 1024 vector elements
    const ulonglong2* yp =
        reinterpret_cast<const ulonglong2*>(g_y + (size_t)b * CR * HWPX + px0) + q;

    #pragma unroll
    for (int ti = 0; ti < 5; ++ti) {
        // ---- conv2 partial: 5 taps of row ti over 64 reduced channels ----
        u64 ka0[5], ka1[5];
        #pragma unroll
        for (int j = 0; j < 5; ++j) { ka0[j] = 0ull; ka1[j] = 0ull; }

        ulonglong2 yv = yp[0];
        #pragma unroll 4
        for (int cr = 0; cr < 64; ++cr) {
            ulonglong2 yn = (cr < 63) ? yp[(cr + 1) * (HWPX / 4)] : yv;  // FIXED stride
            const u64* wr = w2d + cr * 30 + ti * 6;
            ulonglong2 w01 = *reinterpret_cast<const ulonglong2*>(wr);
            ulonglong2 w23 = *reinterpret_cast<const ulonglong2*>(wr + 2);
            u64 w4 = wr[4];
            ka0[0] = ffma2(w01.x, yv.x, ka0[0]);
            ka1[0] = ffma2(w01.x, yv.y, ka1[0]);
            ka0[1] = ffma2(w01.y, yv.x, ka0[1]);
            ka1[1] = ffma2(w01.y, yv.y, ka1[1]);
            ka0[2] = ffma2(w23.x, yv.x, ka0[2]);
            ka1[2] = ffma2(w23.x, yv.y, ka1[2]);
            ka0[3] = ffma2(w23.y, yv.x, ka0[3]);
            ka1[3] = ffma2(w23.y, yv.y, ka1[3]);
            ka0[4] = ffma2(w4,    yv.x, ka0[4]);
            ka1[4] = ffma2(w4,    yv.y, ka1[4]);
            yv = yn;
        }
        // bias for this tap row
        #pragma unroll
        for (int j = 0; j < 5; ++j) {
            float bv = __ldg(b2 + g * 25 + ti * 5 + j);
            u64 bb = pack2(bv, bv);
            ka0[j] = add2(ka0[j], bb);
            ka1[j] = add2(ka1[j], bb);
        }

        // ---- involution contribution of kernel row ti ----
        #pragma unroll
        for (int c = 0; c < 8; ++c) {
            float4 wa = xh4[c * 360 + (r + ti) * 18 + c4];
            float4 wb = xh4[c * 360 + (r + ti) * 18 + c4 + 1];
            u64 p01 = pack2(wa.x, wa.y);
            u64 p12 = pack2(wa.y, wa.z);
            u64 p23 = pack2(wa.z, wa.w);
            u64 p34 = pack2(wa.w, wb.x);
            u64 p45 = pack2(wb.x, wb.y);
            u64 p56 = pack2(wb.y, wb.z);
            u64 p67 = pack2(wb.z, wb.w);
            u64 a = o0[c], bq = o1[c];
            a  = ffma2(ka0[0], p01, a);
            bq = ffma2(ka1[0], p23, bq);
            a  = ffma2(ka0[1], p12, a);
            bq = ffma2(ka1[1], p34, bq);
            a  = ffma2(ka0[2], p23, a);
            bq = ffma2(ka1[2], p45, bq);
            a  = ffma2(ka0[3], p34, a);
            bq = ffma2(ka1[3], p56, bq);
            a  = ffma2(ka0[4], p45, a);
            bq = ffma2(ka1[4], p67, bq);
            o0[c] = a; o1[c] = bq;
        }
    }

    // ---- store ----
    float* ob = out + ((size_t)b * CIN + g * GCH) * HWPX + px0 + 4 * q;
    #pragma unroll
    for (int c = 0; c < 8; ++c) {
        float2 f0 = unpack2(o0[c]);
        float2 f1 = unpack2(o1[c]);
        float4 rv; rv.x = f0.x; rv.y = f0.y; rv.z = f1.x; rv.w = f1.y;
        *reinterpret_cast<float4*>(ob + (size_t)c * HWPX) = rv;
    }
}

// ---------------------------------------------------------------------------
extern "C" void kernel_launch(void* const* d_in, const int* in_sizes, int n_in,
                              void* d_out, int out_size)
{
    const float* x   = (const float*)d_in[0];
    const float* w1  = (const float*)d_in[1];
    const float* b1  = (const float*)d_in[2];
    const float* gma = (const float*)d_in[3];
    const float* bta = (const float*)d_in[4];
    const float* mu  = (const float*)d_in[5];
    const float* var = (const float*)d_in[6];
    const float* w2  = (const float*)d_in[7];
    const float* b2  = (const float*)d_in[8];
    float* out = (float*)d_out;

    const int SMEM1 = 65536;            // w1t
    const int SMEM2 = 46080 + 15360;    // 61440 B
    cudaFuncSetAttribute(k1_conv1, cudaFuncAttributeMaxDynamicSharedMemorySize, SMEM1);
    cudaFuncSetAttribute(k2_fused, cudaFuncAttributeMaxDynamicSharedMemorySize, SMEM2);

    k1_conv1<<<dim3(64, 8), 256, SMEM1>>>(x, w1, b1, gma, bta, mu, var);
    k2_fused<<<dim3(4, 32, 8), 256, SMEM2>>>(x, w2, b2, out);
}